// round 3
// baseline (speedup 1.0000x reference)
#include <cuda_runtime.h>
#include <cuda_bf16.h>
#include <math.h>

// Problem constants (fixed by the reference)
#define NN   50000
#define EE   800000
#define DIN  128
#define HH   256
#define CC   47
#define CP   48      // padded class dim

// ---------------- scratch (device globals; no allocations allowed) ----------
__device__ float g_aggx  [(size_t)NN * DIN];  // 25.6 MB  sum of x over in-edges
__device__ float g_h1    [(size_t)NN * HH];   // 51.2 MB  layer-1 activations
__device__ float g_aggh  [(size_t)NN * HH];   // 51.2 MB  sum of h1 over in-edges
__device__ float g_logits[(size_t)NN * CP];   //  9.6 MB  final logits
__device__ int   g_deg   [NN];
__device__ float g_acc   [2];                 // {sum nll, count}
__device__ int   g_maskwide;                  // 1 if mask words all <=1 (int32 mode)

__device__ __forceinline__ void red4(float* p, float4 v) {
    asm volatile("red.global.add.v4.f32 [%0], {%1,%2,%3,%4};"
                 :: "l"(p), "f"(v.x), "f"(v.y), "f"(v.z), "f"(v.w) : "memory");
}

// ---------------- K0: detect mask dtype --------------------------------------
// If train_mask was widened to int32, every 4-byte word is 0 or 1.
// If it is packed bytes, random 0/1 bytes produce words > 1 with certainty.
__global__ void k_maskprobe(const unsigned int* __restrict__ mw) {
    int i = blockIdx.x * blockDim.x + threadIdx.x;
    if (i >= NN / 4) return;                    // valid range in BOTH layouts
    if (mw[i] > 1u) atomicExch(&g_maskwide, 0);
}

// ---------------- K1: degree count + scatter-sum of x -----------------------
// one warp per edge; lane handles a float4 chunk of the 128-dim feature
__global__ void k_scatter_x(const float* __restrict__ x,
                            const int* __restrict__ row,
                            const int* __restrict__ col) {
    int w = (blockIdx.x * blockDim.x + threadIdx.x) >> 5;
    int lane = threadIdx.x & 31;
    if (w >= EE) return;
    int dst = row[w], src = col[w];
    if (lane == 0) atomicAdd(&g_deg[dst], 1);
    float4 v = *reinterpret_cast<const float4*>(x + (size_t)src * DIN + lane * 4);
    red4(g_aggx + (size_t)dst * DIN + lane * 4, v);
}

// ---------------- GEMM1: h1 = relu([aggx*inv | x] @ [w1n; w1s] + b) ---------
#define BM 64
#define BN 64
#define BK 16
__global__ void k_gemm1(const float* __restrict__ x,
                        const float* __restrict__ w1n, const float* __restrict__ b1n,
                        const float* __restrict__ w1s, const float* __restrict__ b1s) {
    __shared__ float As[BK][BM + 4];
    __shared__ float Bs[BK][BN];
    __shared__ float sinv[BM];

    int tid  = threadIdx.x;
    int row0 = blockIdx.y * BM;
    int col0 = blockIdx.x * BN;

    if (tid < BM) {
        int r = row0 + tid;
        float inv = 0.f;
        if (r < NN) { int d = g_deg[r]; inv = d > 0 ? 1.0f / (float)d : 0.f; }
        sinv[tid] = inv;
    }
    __syncthreads();

    float acc[4][4] = {};
    int ty = tid >> 4, tx = tid & 15;

    for (int k0 = 0; k0 < 2 * DIN; k0 += BK) {
        #pragma unroll
        for (int it = 0; it < 4; ++it) {
            int kk = tid & 15;
            int r  = (tid >> 4) + it * 16;
            int grow = row0 + r;
            int gk   = k0 + kk;
            float v = 0.f;
            if (grow < NN) {
                if (gk < DIN) v = g_aggx[(size_t)grow * DIN + gk] * sinv[r];
                else          v = x[(size_t)grow * DIN + (gk - DIN)];
            }
            As[kk][r] = v;
        }
        #pragma unroll
        for (int it = 0; it < 4; ++it) {
            int j  = tid & 63;
            int kk = (tid >> 6) + it * 4;
            int gk = k0 + kk;
            int gj = col0 + j;
            Bs[kk][j] = (gk < DIN) ? w1n[gk * HH + gj] : w1s[(gk - DIN) * HH + gj];
        }
        __syncthreads();
        #pragma unroll
        for (int kk = 0; kk < BK; ++kk) {
            float4 a = *reinterpret_cast<const float4*>(&As[kk][ty * 4]);
            float4 b = *reinterpret_cast<const float4*>(&Bs[kk][tx * 4]);
            float av[4] = {a.x, a.y, a.z, a.w};
            float bv[4] = {b.x, b.y, b.z, b.w};
            #pragma unroll
            for (int i = 0; i < 4; i++)
                #pragma unroll
                for (int j = 0; j < 4; j++)
                    acc[i][j] += av[i] * bv[j];
        }
        __syncthreads();
    }

    #pragma unroll
    for (int i = 0; i < 4; i++) {
        int grow = row0 + ty * 4 + i;
        if (grow >= NN) continue;
        #pragma unroll
        for (int j = 0; j < 4; j++) {
            int gc = col0 + tx * 4 + j;
            float v = acc[i][j] + b1n[gc] + b1s[gc];
            g_h1[(size_t)grow * HH + gc] = fmaxf(v, 0.f);
        }
    }
}

// ---------------- K2: scatter-sum of h1 (256-dim) ----------------------------
// one warp per edge; each lane handles 2 float4 chunks (64 total)
__global__ void k_scatter_h(const int* __restrict__ row,
                            const int* __restrict__ col) {
    int w = (blockIdx.x * blockDim.x + threadIdx.x) >> 5;
    int lane = threadIdx.x & 31;
    if (w >= EE) return;
    int dst = row[w], src = col[w];
    const float* sp = g_h1   + (size_t)src * HH;
    float*       dp = g_aggh + (size_t)dst * HH;
    float4 v0 = *reinterpret_cast<const float4*>(sp + lane * 4);
    float4 v1 = *reinterpret_cast<const float4*>(sp + 128 + lane * 4);
    red4(dp + lane * 4,       v0);
    red4(dp + 128 + lane * 4, v1);
}

// ---------------- GEMM2: logits = [aggh*inv | h1] @ [w2n; w2s] + biases ------
// virtual K = 512, N = 47 (single column block of 64)
__global__ void k_gemm2(const float* __restrict__ w2n, const float* __restrict__ b2n,
                        const float* __restrict__ w2s, const float* __restrict__ b2s) {
    __shared__ float As[BK][BM + 4];
    __shared__ float Bs[BK][BN];
    __shared__ float sinv[BM];

    int tid  = threadIdx.x;
    int row0 = blockIdx.y * BM;

    if (tid < BM) {
        int r = row0 + tid;
        float inv = 0.f;
        if (r < NN) { int d = g_deg[r]; inv = d > 0 ? 1.0f / (float)d : 0.f; }
        sinv[tid] = inv;
    }
    __syncthreads();

    float acc[4][4] = {};
    int ty = tid >> 4, tx = tid & 15;

    for (int k0 = 0; k0 < 2 * HH; k0 += BK) {
        #pragma unroll
        for (int it = 0; it < 4; ++it) {
            int kk = tid & 15;
            int r  = (tid >> 4) + it * 16;
            int grow = row0 + r;
            int gk   = k0 + kk;
            float v = 0.f;
            if (grow < NN) {
                if (gk < HH) v = g_aggh[(size_t)grow * HH + gk] * sinv[r];
                else         v = g_h1[(size_t)grow * HH + (gk - HH)];
            }
            As[kk][r] = v;
        }
        #pragma unroll
        for (int it = 0; it < 4; ++it) {
            int j  = tid & 63;
            int kk = (tid >> 6) + it * 4;
            int gk = k0 + kk;
            float v = 0.f;
            if (j < CC) {
                if (gk < HH) v = w2n[gk * CC + j];
                else         v = w2s[(gk - HH) * CC + j];
            }
            Bs[kk][j] = v;
        }
        __syncthreads();
        #pragma unroll
        for (int kk = 0; kk < BK; ++kk) {
            float4 a = *reinterpret_cast<const float4*>(&As[kk][ty * 4]);
            float4 b = *reinterpret_cast<const float4*>(&Bs[kk][tx * 4]);
            float av[4] = {a.x, a.y, a.z, a.w};
            float bv[4] = {b.x, b.y, b.z, b.w};
            #pragma unroll
            for (int i = 0; i < 4; i++)
                #pragma unroll
                for (int j = 0; j < 4; j++)
                    acc[i][j] += av[i] * bv[j];
        }
        __syncthreads();
    }

    #pragma unroll
    for (int i = 0; i < 4; i++) {
        int grow = row0 + ty * 4 + i;
        if (grow >= NN) continue;
        #pragma unroll
        for (int j = 0; j < 4; j++) {
            int gj = tx * 4 + j;
            if (gj < CC)
                g_logits[(size_t)grow * CP + gj] = acc[i][j] + b2n[gj] + b2s[gj];
        }
    }
}

// ---------------- K4: log_softmax -> masked NLL sum --------------------------
// one warp per node; mask read per detected dtype
__global__ void k_loss(const int* __restrict__ y,
                       const void* __restrict__ maskp) {
    int w = (blockIdx.x * blockDim.x + threadIdx.x) >> 5;
    int lane = threadIdx.x & 31;
    if (w >= NN) return;
    const float* lg = g_logits + (size_t)w * CP;

    int j2 = lane + 32;
    float l1 = lg[lane];                       // lane in [0,32) < 47
    float l2 = (j2 < CC) ? lg[j2] : -1e30f;

    float m = fmaxf(l1, l2);
    #pragma unroll
    for (int o = 16; o; o >>= 1) m = fmaxf(m, __shfl_xor_sync(0xffffffffu, m, o));
    float se = expf(l1 - m) + ((j2 < CC) ? expf(l2 - m) : 0.f);
    #pragma unroll
    for (int o = 16; o; o >>= 1) se += __shfl_xor_sync(0xffffffffu, se, o);

    if (lane == 0) {
        bool tm;
        if (g_maskwide)
            tm = ((const int*)maskp)[w] != 0;
        else
            tm = ((const unsigned char*)maskp)[w] != 0;
        if (tm) {
            float nll = m + logf(se) - lg[y[w]];
            atomicAdd(&g_acc[0], nll);
            atomicAdd(&g_acc[1], 1.0f);
        }
    }
}

__global__ void k_fin(float* out) {
    out[0] = g_acc[0] / fmaxf(g_acc[1], 1.0f);
}

__global__ void k_initflag() { g_maskwide = 1; }

// ---------------- host launcher ---------------------------------------------
extern "C" void kernel_launch(void* const* d_in, const int* in_sizes, int n_in,
                              void* d_out, int out_size) {
    const float* x    = (const float*)d_in[0];
    const int*   row  = (const int*)d_in[1];
    const int*   col  = (const int*)d_in[2];
    const int*   y    = (const int*)d_in[3];
    const void*  mask = d_in[4];
    const float* w1n = (const float*)d_in[5];
    const float* b1n = (const float*)d_in[6];
    const float* w1s = (const float*)d_in[7];
    const float* b1s = (const float*)d_in[8];
    const float* w2n = (const float*)d_in[9];
    const float* b2n = (const float*)d_in[10];
    const float* w2s = (const float*)d_in[11];
    const float* b2s = (const float*)d_in[12];
    float* out = (float*)d_out;

    void *p_aggx, *p_aggh, *p_deg, *p_acc;
    cudaGetSymbolAddress(&p_aggx, g_aggx);
    cudaGetSymbolAddress(&p_aggh, g_aggh);
    cudaGetSymbolAddress(&p_deg,  g_deg);
    cudaGetSymbolAddress(&p_acc,  g_acc);

    cudaMemsetAsync(p_aggx, 0, (size_t)NN * DIN * sizeof(float));
    cudaMemsetAsync(p_aggh, 0, (size_t)NN * HH * sizeof(float));
    cudaMemsetAsync(p_deg,  0, NN * sizeof(int));
    cudaMemsetAsync(p_acc,  0, 2 * sizeof(float));

    // K0: mask dtype probe
    k_initflag<<<1, 1>>>();
    k_maskprobe<<<(NN / 4 + 255) / 256, 256>>>((const unsigned int*)mask);

    // K1: scatter x + degree (one warp per edge)
    {
        long long threads = (long long)EE * 32;
        int blocks = (int)((threads + 255) / 256);
        k_scatter_x<<<blocks, 256>>>(x, row, col);
    }
    // GEMM1: h1
    {
        dim3 grid(HH / BN, (NN + BM - 1) / BM);
        k_gemm1<<<grid, 256>>>(x, w1n, b1n, w1s, b1s);
    }
    // K2: scatter h1 (one warp per edge)
    {
        long long threads = (long long)EE * 32;
        int blocks = (int)((threads + 255) / 256);
        k_scatter_h<<<blocks, 256>>>(row, col);
    }
    // GEMM2: logits
    {
        dim3 grid(1, (NN + BM - 1) / BM);
        k_gemm2<<<grid, 256>>>(w2n, b2n, w2s, b2s);
    }
    // K4: loss reduction (one warp per node)
    {
        long long threads = (long long)NN * 32;
        int blocks = (int)((threads + 255) / 256);
        k_loss<<<blocks, 256>>>(y, mask);
    }
    k_fin<<<1, 1>>>(out);
}

// round 4
// speedup vs baseline: 1.8144x; 1.8144x over previous
#include <cuda_runtime.h>
#include <cuda_bf16.h>
#include <math.h>

// Problem constants (fixed by the reference)
#define NN   50000
#define EE   800000
#define DIN  128
#define HH   256
#define CC   47
#define CP   48      // padded class dim

// ---------------- scratch (device globals; no allocations allowed) ----------
__device__ float g_aggx  [(size_t)NN * DIN];  // 25.6 MB  sum of x over in-edges
__device__ float g_h1    [(size_t)NN * HH];   // 51.2 MB  layer-1 activations
__device__ float g_z     [(size_t)NN * CP];   //  9.6 MB  h1 @ w2n (pre-aggregation)
__device__ float g_s     [(size_t)NN * CP];   //  9.6 MB  h1 @ w2s (self path)
__device__ float g_aggz  [(size_t)NN * CP];   //  9.6 MB  sum of z over in-edges
__device__ int   g_deg   [NN];
__device__ float g_acc   [2];                 // {sum nll, count}
__device__ int   g_maskwide;                  // 1 if mask is int32 0/1 words

__device__ __forceinline__ void red4(float* p, float4 v) {
    asm volatile("red.global.add.v4.f32 [%0], {%1,%2,%3,%4};"
                 :: "l"(p), "f"(v.x), "f"(v.y), "f"(v.z), "f"(v.w) : "memory");
}

__device__ __forceinline__ unsigned f2tf(float x) {
    unsigned u;
    asm("cvt.rna.tf32.f32 %0, %1;" : "=r"(u) : "f"(x));
    return u;
}

__device__ __forceinline__ void mma_tf32(float c[4],
                                         unsigned a0, unsigned a1, unsigned a2, unsigned a3,
                                         unsigned b0, unsigned b1) {
    asm volatile("mma.sync.aligned.m16n8k8.row.col.f32.tf32.tf32.f32 "
                 "{%0,%1,%2,%3},{%4,%5,%6,%7},{%8,%9},{%0,%1,%2,%3};"
                 : "+f"(c[0]), "+f"(c[1]), "+f"(c[2]), "+f"(c[3])
                 : "r"(a0), "r"(a1), "r"(a2), "r"(a3), "r"(b0), "r"(b1));
}

// ---------------- K0: detect mask dtype --------------------------------------
__global__ void k_initflag() { g_maskwide = 1; }
__global__ void k_maskprobe(const unsigned int* __restrict__ mw) {
    int i = blockIdx.x * blockDim.x + threadIdx.x;
    if (i >= NN / 4) return;
    if (mw[i] > 1u) atomicExch(&g_maskwide, 0);
}

// ---------------- K1: degree count + scatter-sum of x -----------------------
__global__ void k_scatter_x(const float* __restrict__ x,
                            const int* __restrict__ row,
                            const int* __restrict__ col) {
    int w = (blockIdx.x * blockDim.x + threadIdx.x) >> 5;
    int lane = threadIdx.x & 31;
    if (w >= EE) return;
    int dst = row[w], src = col[w];
    if (lane == 0) atomicAdd(&g_deg[dst], 1);
    float4 v = *reinterpret_cast<const float4*>(x + (size_t)src * DIN + lane * 4);
    red4(g_aggx + (size_t)dst * DIN + lane * 4, v);
}

// ---------------- GEMM1 (TF32 mma): h1 = relu([aggx*inv|x] @ [w1n;w1s] + b) --
// block tile 128x128x32, 8 warps in 2(m) x 4(n), warp tile 64x32
__global__ __launch_bounds__(256) void k_gemm1_mma(
        const float* __restrict__ x,
        const float* __restrict__ w1n, const float* __restrict__ b1n,
        const float* __restrict__ w1s, const float* __restrict__ b1s) {
    __shared__ unsigned As[128][36];   // [m][k], pad 4
    __shared__ unsigned Bs[32][136];   // [k][n], pad 8
    __shared__ float sinv[128];
    __shared__ float sbias[128];

    int tid  = threadIdx.x;
    int row0 = blockIdx.y * 128;
    int col0 = blockIdx.x * 128;

    if (tid < 128) {
        int r = row0 + tid;
        float v = 0.f;
        if (r < NN) { int d = g_deg[r]; v = d > 0 ? 1.0f / (float)d : 0.f; }
        sinv[tid] = v;
    } else {
        int n = col0 + tid - 128;
        sbias[tid - 128] = b1n[n] + b1s[n];
    }
    __syncthreads();

    int lane = tid & 31, wid = tid >> 5;
    int g = lane >> 2, tg = lane & 3;
    int m_w = (wid & 1) * 64;
    int n_w = (wid >> 1) * 32;

    float acc[4][4][4] = {};

    for (int k0 = 0; k0 < 2 * DIN; k0 += 32) {
        // load A tile: [m][k], thread: m = tid/8 + i*32, k4 = (tid&7)*4
        {
            int k4 = (tid & 7) * 4;
            #pragma unroll
            for (int i = 0; i < 4; ++i) {
                int ml = (tid >> 3) + i * 32;
                int gm = row0 + ml;
                float4 v = make_float4(0.f, 0.f, 0.f, 0.f);
                float s = 1.f;
                if (gm < NN) {
                    if (k0 < DIN) {
                        v = *reinterpret_cast<const float4*>(g_aggx + (size_t)gm * DIN + k0 + k4);
                        s = sinv[ml];
                    } else {
                        v = *reinterpret_cast<const float4*>(x + (size_t)gm * DIN + (k0 - DIN) + k4);
                    }
                }
                As[ml][k4 + 0] = f2tf(v.x * s);
                As[ml][k4 + 1] = f2tf(v.y * s);
                As[ml][k4 + 2] = f2tf(v.z * s);
                As[ml][k4 + 3] = f2tf(v.w * s);
            }
        }
        // load B tile: [k][n], thread: kk = tid/32 + i*8, n4 = (tid&31)*4
        {
            int n4 = (lane) * 4;
            #pragma unroll
            for (int i = 0; i < 4; ++i) {
                int kk = wid + i * 8;
                int gk = k0 + kk;
                const float* wp = (gk < DIN) ? (w1n + (size_t)gk * HH + col0 + n4)
                                             : (w1s + (size_t)(gk - DIN) * HH + col0 + n4);
                float4 b = *reinterpret_cast<const float4*>(wp);
                Bs[kk][n4 + 0] = f2tf(b.x);
                Bs[kk][n4 + 1] = f2tf(b.y);
                Bs[kk][n4 + 2] = f2tf(b.z);
                Bs[kk][n4 + 3] = f2tf(b.w);
            }
        }
        __syncthreads();

        #pragma unroll
        for (int ks = 0; ks < 4; ++ks) {
            unsigned af[4][4];
            #pragma unroll
            for (int mt = 0; mt < 4; ++mt) {
                int m = m_w + mt * 16;
                int kk = ks * 8 + tg;
                af[mt][0] = As[m + g][kk];
                af[mt][1] = As[m + g + 8][kk];
                af[mt][2] = As[m + g][kk + 4];
                af[mt][3] = As[m + g + 8][kk + 4];
            }
            unsigned bf[4][2];
            #pragma unroll
            for (int nt = 0; nt < 4; ++nt) {
                int n = n_w + nt * 8 + g;
                bf[nt][0] = Bs[ks * 8 + tg][n];
                bf[nt][1] = Bs[ks * 8 + tg + 4][n];
            }
            #pragma unroll
            for (int mt = 0; mt < 4; ++mt)
                #pragma unroll
                for (int nt = 0; nt < 4; ++nt)
                    mma_tf32(acc[mt][nt], af[mt][0], af[mt][1], af[mt][2], af[mt][3],
                             bf[nt][0], bf[nt][1]);
        }
        __syncthreads();
    }

    // epilogue: bias + relu, float2 stores
    #pragma unroll
    for (int mt = 0; mt < 4; ++mt) {
        int mb = row0 + m_w + mt * 16 + g;
        #pragma unroll
        for (int nt = 0; nt < 4; ++nt) {
            int nl = n_w + nt * 8 + 2 * tg;
            int gn = col0 + nl;
            float b0 = sbias[nl], b1 = sbias[nl + 1];
            if (mb < NN) {
                float2 r;
                r.x = fmaxf(acc[mt][nt][0] + b0, 0.f);
                r.y = fmaxf(acc[mt][nt][1] + b1, 0.f);
                *reinterpret_cast<float2*>(g_h1 + (size_t)mb * HH + gn) = r;
            }
            if (mb + 8 < NN) {
                float2 r;
                r.x = fmaxf(acc[mt][nt][2] + b0, 0.f);
                r.y = fmaxf(acc[mt][nt][3] + b1, 0.f);
                *reinterpret_cast<float2*>(g_h1 + (size_t)(mb + 8) * HH + gn) = r;
            }
        }
    }
}

// ---------------- GEMM2 (TF32 mma): [z|s] = h1 @ [w2n|w2s] -------------------
// block tile 128x96x32, 8 warps in 4(m) x 2(n), warp tile 32x48
__global__ __launch_bounds__(256) void k_gemm2_mma(
        const float* __restrict__ w2n, const float* __restrict__ w2s) {
    __shared__ unsigned As[128][36];   // [m][k]
    __shared__ unsigned Bs[32][104];   // [k][n], 96 + pad 8

    int tid  = threadIdx.x;
    int row0 = blockIdx.y * 128;

    int lane = tid & 31, wid = tid >> 5;
    int g = lane >> 2, tg = lane & 3;
    int m_w = (wid & 3) * 32;
    int n_w = (wid >> 2) * 48;

    float acc[2][6][4] = {};

    for (int k0 = 0; k0 < HH; k0 += 32) {
        {
            int k4 = (tid & 7) * 4;
            #pragma unroll
            for (int i = 0; i < 4; ++i) {
                int ml = (tid >> 3) + i * 32;
                int gm = row0 + ml;
                float4 v = make_float4(0.f, 0.f, 0.f, 0.f);
                if (gm < NN)
                    v = *reinterpret_cast<const float4*>(g_h1 + (size_t)gm * HH + k0 + k4);
                As[ml][k4 + 0] = f2tf(v.x);
                As[ml][k4 + 1] = f2tf(v.y);
                As[ml][k4 + 2] = f2tf(v.z);
                As[ml][k4 + 3] = f2tf(v.w);
            }
        }
        {
            #pragma unroll
            for (int i = 0; i < 12; ++i) {
                int idx = tid + i * 256;        // 32*96 = 3072 elements
                int kk = idx / 96, n = idx % 96;
                int gk = k0 + kk;
                float v = 0.f;
                if (n < CP) { if (n < CC) v = w2n[(size_t)gk * CC + n]; }
                else        { int n2 = n - CP; if (n2 < CC) v = w2s[(size_t)gk * CC + n2]; }
                Bs[kk][n] = f2tf(v);
            }
        }
        __syncthreads();

        #pragma unroll
        for (int ks = 0; ks < 4; ++ks) {
            unsigned af[2][4];
            #pragma unroll
            for (int mt = 0; mt < 2; ++mt) {
                int m = m_w + mt * 16;
                int kk = ks * 8 + tg;
                af[mt][0] = As[m + g][kk];
                af[mt][1] = As[m + g + 8][kk];
                af[mt][2] = As[m + g][kk + 4];
                af[mt][3] = As[m + g + 8][kk + 4];
            }
            unsigned bf[6][2];
            #pragma unroll
            for (int nt = 0; nt < 6; ++nt) {
                int n = n_w + nt * 8 + g;
                bf[nt][0] = Bs[ks * 8 + tg][n];
                bf[nt][1] = Bs[ks * 8 + tg + 4][n];
            }
            #pragma unroll
            for (int mt = 0; mt < 2; ++mt)
                #pragma unroll
                for (int nt = 0; nt < 6; ++nt)
                    mma_tf32(acc[mt][nt], af[mt][0], af[mt][1], af[mt][2], af[mt][3],
                             bf[nt][0], bf[nt][1]);
        }
        __syncthreads();
    }

    #pragma unroll
    for (int mt = 0; mt < 2; ++mt) {
        int mb = row0 + m_w + mt * 16 + g;
        #pragma unroll
        for (int nt = 0; nt < 6; ++nt) {
            int n = n_w + nt * 8 + 2 * tg;
            float* dst = (n < CP) ? (g_z + n) : (g_s + (n - CP));
            if (mb < NN) {
                float2 r = make_float2(acc[mt][nt][0], acc[mt][nt][1]);
                *reinterpret_cast<float2*>(dst + (size_t)mb * CP) = r;
            }
            if (mb + 8 < NN) {
                float2 r = make_float2(acc[mt][nt][2], acc[mt][nt][3]);
                *reinterpret_cast<float2*>(dst + (size_t)(mb + 8) * CP) = r;
            }
        }
    }
}

// ---------------- K3: scatter-sum of z (48-dim) ------------------------------
__global__ void k_scatter_z(const int* __restrict__ row,
                            const int* __restrict__ col) {
    int gid = blockIdx.x * blockDim.x + threadIdx.x;
    int e = gid >> 4;
    int c = gid & 15;
    if (e >= EE || c >= 12) return;
    int dst = row[e], src = col[e];
    float4 v = *reinterpret_cast<const float4*>(g_z + (size_t)src * CP + c * 4);
    red4(g_aggz + (size_t)dst * CP + c * 4, v);
}

// ---------------- K4: log_softmax -> masked NLL sum --------------------------
__global__ void k_loss(const int* __restrict__ y,
                       const void* __restrict__ maskp,
                       const float* __restrict__ b2n,
                       const float* __restrict__ b2s) {
    int w = (blockIdx.x * blockDim.x + threadIdx.x) >> 5;
    int lane = threadIdx.x & 31;
    if (w >= NN) return;
    int d = g_deg[w];
    float inv = d > 0 ? 1.0f / (float)d : 0.f;
    const float* az = g_aggz + (size_t)w * CP;
    const float* ss = g_s    + (size_t)w * CP;

    int j2 = lane + 32;
    float l1 = az[lane] * inv + ss[lane] + b2n[lane] + b2s[lane];
    float l2 = -1e30f;
    if (j2 < CC) l2 = az[j2] * inv + ss[j2] + b2n[j2] + b2s[j2];

    float m = fmaxf(l1, l2);
    #pragma unroll
    for (int o = 16; o; o >>= 1) m = fmaxf(m, __shfl_xor_sync(0xffffffffu, m, o));
    float se = expf(l1 - m) + ((j2 < CC) ? expf(l2 - m) : 0.f);
    #pragma unroll
    for (int o = 16; o; o >>= 1) se += __shfl_xor_sync(0xffffffffu, se, o);

    if (lane == 0) {
        bool tm = g_maskwide ? (((const int*)maskp)[w] != 0)
                             : (((const unsigned char*)maskp)[w] != 0);
        if (tm) {
            int yy = y[w];
            float ly = az[yy] * inv + ss[yy] + b2n[yy] + b2s[yy];
            float nll = m + logf(se) - ly;
            atomicAdd(&g_acc[0], nll);
            atomicAdd(&g_acc[1], 1.0f);
        }
    }
}

__global__ void k_fin(float* out) {
    out[0] = g_acc[0] / fmaxf(g_acc[1], 1.0f);
}

// ---------------- host launcher ---------------------------------------------
extern "C" void kernel_launch(void* const* d_in, const int* in_sizes, int n_in,
                              void* d_out, int out_size) {
    const float* x    = (const float*)d_in[0];
    const int*   row  = (const int*)d_in[1];
    const int*   col  = (const int*)d_in[2];
    const int*   y    = (const int*)d_in[3];
    const void*  mask = d_in[4];
    const float* w1n = (const float*)d_in[5];
    const float* b1n = (const float*)d_in[6];
    const float* w1s = (const float*)d_in[7];
    const float* b1s = (const float*)d_in[8];
    const float* w2n = (const float*)d_in[9];
    const float* b2n = (const float*)d_in[10];
    const float* w2s = (const float*)d_in[11];
    const float* b2s = (const float*)d_in[12];
    float* out = (float*)d_out;

    void *p_aggx, *p_aggz, *p_deg, *p_acc;
    cudaGetSymbolAddress(&p_aggx, g_aggx);
    cudaGetSymbolAddress(&p_aggz, g_aggz);
    cudaGetSymbolAddress(&p_deg,  g_deg);
    cudaGetSymbolAddress(&p_acc,  g_acc);

    cudaMemsetAsync(p_aggx, 0, (size_t)NN * DIN * sizeof(float));
    cudaMemsetAsync(p_aggz, 0, (size_t)NN * CP * sizeof(float));
    cudaMemsetAsync(p_deg,  0, NN * sizeof(int));
    cudaMemsetAsync(p_acc,  0, 2 * sizeof(float));

    k_initflag<<<1, 1>>>();
    k_maskprobe<<<(NN / 4 + 255) / 256, 256>>>((const unsigned int*)mask);

    {   // K1: scatter x + degree
        long long threads = (long long)EE * 32;
        k_scatter_x<<<(int)((threads + 255) / 256), 256>>>(x, row, col);
    }
    {   // GEMM1 (tf32 mma)
        dim3 grid(HH / 128, (NN + 127) / 128);
        k_gemm1_mma<<<grid, 256>>>(x, w1n, b1n, w1s, b1s);
    }
    {   // GEMM2 (tf32 mma)
        dim3 grid(1, (NN + 127) / 128);
        k_gemm2_mma<<<grid, 256>>>(w2n, w2s);
    }
    {   // K3: scatter z
        long long threads = (long long)EE * 16;
        k_scatter_z<<<(int)((threads + 255) / 256), 256>>>(row, col);
    }
    {   // K4: loss
        long long threads = (long long)NN * 32;
        k_loss<<<(int)((threads + 255) / 256), 256>>>(y, mask, b2n, b2s);
    }
    k_fin<<<1, 1>>>(out);
}

// round 5
// speedup vs baseline: 2.7587x; 1.5205x over previous
#include <cuda_runtime.h>
#include <cuda_bf16.h>
#include <math.h>

#define NN   50000
#define EE   800000
#define DIN  128
#define HH   256
#define CC   47
#define CP   48

// ---------------- scratch (device globals) -----------------------------------
__device__ float g_aggx [(size_t)NN * DIN];  // tf32 mean of x over in-edges
__device__ float g_xc   [(size_t)NN * DIN];  // tf32 copy of x
__device__ float g_h1   [(size_t)NN * HH];   // tf32 layer-1 activations
__device__ float g_w1   [256 * HH];          // tf32 packed [w1n; w1s]
__device__ float g_w2   [HH * 96];           // tf32 packed [w2n | w2s] (padded 48+48)
__device__ float g_z    [(size_t)NN * CP];
__device__ float g_s    [(size_t)NN * CP];
__device__ float g_aggz [(size_t)NN * CP];   // mean of z over in-edges
__device__ int   g_deg  [NN];
__device__ int   g_rowptr[NN];
__device__ int   g_cursor[NN];
__device__ int   g_adj  [EE];
__device__ int   g_bsum [256];
__device__ float g_acc  [2];
__device__ int   g_maskwide;

__device__ __forceinline__ unsigned f2tf(float x) {
    unsigned u;
    asm("cvt.rna.tf32.f32 %0, %1;" : "=r"(u) : "f"(x));
    return u;
}
__device__ __forceinline__ float tf(float x) { return __uint_as_float(f2tf(x)); }

__device__ __forceinline__ void mma_tf32(float c[4],
                                         unsigned a0, unsigned a1, unsigned a2, unsigned a3,
                                         unsigned b0, unsigned b1) {
    asm volatile("mma.sync.aligned.m16n8k8.row.col.f32.tf32.tf32.f32 "
                 "{%0,%1,%2,%3},{%4,%5,%6,%7},{%8,%9},{%0,%1,%2,%3};"
                 : "+f"(c[0]), "+f"(c[1]), "+f"(c[2]), "+f"(c[3])
                 : "r"(a0), "r"(a1), "r"(a2), "r"(a3), "r"(b0), "r"(b1));
}

__device__ __forceinline__ void cpa16(void* dst, const void* src, bool p) {
    unsigned d = (unsigned)__cvta_generic_to_shared(dst);
    int sz = p ? 16 : 0;
    asm volatile("cp.async.ca.shared.global [%0], [%1], 16, %2;"
                 :: "r"(d), "l"(src), "r"(sz) : "memory");
}

// ---------------- misc small kernels -----------------------------------------
__global__ void k_initflag() { g_maskwide = 1; }
__global__ void k_maskprobe(const unsigned int* __restrict__ mw) {
    int i = blockIdx.x * blockDim.x + threadIdx.x;
    if (i >= NN / 4) return;
    if (mw[i] > 1u) atomicExch(&g_maskwide, 0);
}

__global__ void k_deg(const int* __restrict__ row) {
    int e = blockIdx.x * blockDim.x + threadIdx.x;
    if (e < EE) atomicAdd(&g_deg[row[e]], 1);
}

// exclusive scan of g_deg -> g_rowptr (3-phase)
__global__ void k_scan1() {
    __shared__ int sh[256];
    int i = blockIdx.x * 256 + threadIdx.x;
    int v = (i < NN) ? g_deg[i] : 0;
    sh[threadIdx.x] = v;
    __syncthreads();
    for (int o = 1; o < 256; o <<= 1) {
        int t = (threadIdx.x >= o) ? sh[threadIdx.x - o] : 0;
        __syncthreads();
        sh[threadIdx.x] += t;
        __syncthreads();
    }
    int incl = sh[threadIdx.x];
    if (i < NN) g_rowptr[i] = incl - v;
    if (threadIdx.x == 255) g_bsum[blockIdx.x] = incl;
}
__global__ void k_scan2(int nb) {
    __shared__ int sh[256];
    int b = threadIdx.x;
    int v = (b < nb) ? g_bsum[b] : 0;
    sh[b] = v;
    __syncthreads();
    for (int o = 1; o < 256; o <<= 1) {
        int t = (b >= o) ? sh[b - o] : 0;
        __syncthreads();
        sh[b] += t;
        __syncthreads();
    }
    g_bsum[b] = sh[b] - v;
}
__global__ void k_scan3() {
    int i = blockIdx.x * 256 + threadIdx.x;
    if (i >= NN) return;
    int rp = g_rowptr[i] + g_bsum[i >> 8];
    g_rowptr[i] = rp;
    g_cursor[i] = rp;
}

__global__ void k_fill(const int* __restrict__ row, const int* __restrict__ col) {
    int e = blockIdx.x * blockDim.x + threadIdx.x;
    if (e >= EE) return;
    int pos = atomicAdd(&g_cursor[row[e]], 1);
    g_adj[pos] = col[e];
}

// ---------------- prep: tf32-quantized operand buffers -----------------------
__global__ void k_prep_x(const float* __restrict__ x) {
    int i = blockIdx.x * blockDim.x + threadIdx.x;
    if (i >= NN * DIN / 4) return;
    float4 v = reinterpret_cast<const float4*>(x)[i];
    float4 r = make_float4(tf(v.x), tf(v.y), tf(v.z), tf(v.w));
    reinterpret_cast<float4*>(g_xc)[i] = r;
}
__global__ void k_prep_w1(const float* __restrict__ w1n, const float* __restrict__ w1s) {
    int i = blockIdx.x * blockDim.x + threadIdx.x;
    if (i >= 256 * HH) return;
    int k = i >> 8, n = i & 255;
    float v = (k < DIN) ? w1n[k * HH + n] : w1s[(k - DIN) * HH + n];
    g_w1[i] = tf(v);
}
__global__ void k_prep_w2(const float* __restrict__ w2n, const float* __restrict__ w2s) {
    int i = blockIdx.x * blockDim.x + threadIdx.x;
    if (i >= HH * 96) return;
    int k = i / 96, n = i % 96;
    float v = 0.f;
    if (n < CP) { if (n < CC) v = w2n[k * CC + n]; }
    else        { int n2 = n - CP; if (n2 < CC) v = w2s[k * CC + n2]; }
    g_w2[i] = tf(v);
}

// ---------------- agg1: aggx = tf32(mean of x rows) (warp per node) ----------
__global__ void k_agg1(const float* __restrict__ x) {
    int w = (blockIdx.x * blockDim.x + threadIdx.x) >> 5;
    int lane = threadIdx.x & 31;
    if (w >= NN) return;
    int start = g_rowptr[w], d = g_deg[w];
    float4 acc = make_float4(0.f, 0.f, 0.f, 0.f);
    for (int j = 0; j < d; ++j) {
        int s = g_adj[start + j];
        float4 v = *reinterpret_cast<const float4*>(x + (size_t)s * DIN + lane * 4);
        acc.x += v.x; acc.y += v.y; acc.z += v.z; acc.w += v.w;
    }
    float inv = d > 0 ? 1.0f / (float)d : 0.f;
    float4 r = make_float4(tf(acc.x * inv), tf(acc.y * inv), tf(acc.z * inv), tf(acc.w * inv));
    *reinterpret_cast<float4*>(g_aggx + (size_t)w * DIN + lane * 4) = r;
}

// ---------------- GEMM1: h1 = tf32(relu([aggx|xc] @ g_w1 + bias)) ------------
// 128x128x32 tiles, 8 k-tiles, double-buffered cp.async, 8 warps 2(m)x4(n)
#define G1_SMEM_FLOATS (2*128*36 + 2*32*136 + 128)
__global__ __launch_bounds__(256) void k_gemm1_mma(
        const float* __restrict__ b1n, const float* __restrict__ b1s) {
    extern __shared__ float dyns[];
    float* Asf = dyns;                      // [2][128][36]
    float* Bsf = dyns + 2 * 128 * 36;       // [2][32][136]
    float* sbias = Bsf + 2 * 32 * 136;      // [128]

    int tid  = threadIdx.x;
    int row0 = blockIdx.y * 128;
    int col0 = blockIdx.x * 128;

    if (tid < 128) sbias[tid] = b1n[col0 + tid] + b1s[col0 + tid];

    int lane = tid & 31, wid = tid >> 5;
    int g = lane >> 2, tg = lane & 3;
    int m_w = (wid & 1) * 64;
    int n_w = (wid >> 1) * 32;

#define ASF(s,m,k) Asf[((s)*128 + (m))*36 + (k)]
#define BSF(s,kk,n) Bsf[((s)*32 + (kk))*136 + (n)]

    auto load_tiles = [&](int s, int kt) {
        int k0 = kt * 32;
        #pragma unroll
        for (int i = 0; i < 4; ++i) {
            int idx = tid + i * 256;
            int r = idx >> 3, c = idx & 7;
            int gm = row0 + r;
            bool p = gm < NN;
            int gmc = p ? gm : 0;
            const float* src = (k0 < DIN)
                ? g_aggx + (size_t)gmc * DIN + k0 + c * 4
                : g_xc   + (size_t)gmc * DIN + (k0 - DIN) + c * 4;
            cpa16(&ASF(s, r, c * 4), src, p);
        }
        #pragma unroll
        for (int i = 0; i < 4; ++i) {
            int idx = tid + i * 256;
            int r = idx >> 5, c = idx & 31;
            const float* src = g_w1 + (size_t)(k0 + r) * HH + col0 + c * 4;
            cpa16(&BSF(s, r, c * 4), src, true);
        }
    };

    float acc[4][4][4] = {};

    load_tiles(0, 0);
    asm volatile("cp.async.commit_group;" ::: "memory");

    for (int kt = 0; kt < 8; ++kt) {
        if (kt + 1 < 8) {
            load_tiles((kt + 1) & 1, kt + 1);
            asm volatile("cp.async.commit_group;" ::: "memory");
            asm volatile("cp.async.wait_group 1;" ::: "memory");
        } else {
            asm volatile("cp.async.wait_group 0;" ::: "memory");
        }
        __syncthreads();
        int buf = kt & 1;
        #pragma unroll
        for (int ks = 0; ks < 4; ++ks) {
            int kk = ks * 8 + tg;
            unsigned af[4][4];
            #pragma unroll
            for (int mt = 0; mt < 4; ++mt) {
                int m = m_w + mt * 16;
                af[mt][0] = __float_as_uint(ASF(buf, m + g,     kk));
                af[mt][1] = __float_as_uint(ASF(buf, m + g + 8, kk));
                af[mt][2] = __float_as_uint(ASF(buf, m + g,     kk + 4));
                af[mt][3] = __float_as_uint(ASF(buf, m + g + 8, kk + 4));
            }
            unsigned bf[4][2];
            #pragma unroll
            for (int nt = 0; nt < 4; ++nt) {
                int n = n_w + nt * 8 + g;
                bf[nt][0] = __float_as_uint(BSF(buf, kk,     n));
                bf[nt][1] = __float_as_uint(BSF(buf, kk + 4, n));
            }
            #pragma unroll
            for (int mt = 0; mt < 4; ++mt)
                #pragma unroll
                for (int nt = 0; nt < 4; ++nt)
                    mma_tf32(acc[mt][nt], af[mt][0], af[mt][1], af[mt][2], af[mt][3],
                             bf[nt][0], bf[nt][1]);
        }
        __syncthreads();
    }

    #pragma unroll
    for (int mt = 0; mt < 4; ++mt) {
        int mb = row0 + m_w + mt * 16 + g;
        #pragma unroll
        for (int nt = 0; nt < 4; ++nt) {
            int nl = n_w + nt * 8 + 2 * tg;
            int gn = col0 + nl;
            float b0 = sbias[nl], b1 = sbias[nl + 1];
            if (mb < NN) {
                float2 r;
                r.x = tf(fmaxf(acc[mt][nt][0] + b0, 0.f));
                r.y = tf(fmaxf(acc[mt][nt][1] + b1, 0.f));
                *reinterpret_cast<float2*>(g_h1 + (size_t)mb * HH + gn) = r;
            }
            if (mb + 8 < NN) {
                float2 r;
                r.x = tf(fmaxf(acc[mt][nt][2] + b0, 0.f));
                r.y = tf(fmaxf(acc[mt][nt][3] + b1, 0.f));
                *reinterpret_cast<float2*>(g_h1 + (size_t)(mb + 8) * HH + gn) = r;
            }
        }
    }
}

// ---------------- GEMM2: [z|s] = h1 @ g_w2 (128x96x32, 8 warps 4m x 2n) ------
__global__ __launch_bounds__(256) void k_gemm2_mma() {
    __shared__ unsigned As[128][36];
    __shared__ unsigned Bs[32][104];

    int tid  = threadIdx.x;
    int row0 = blockIdx.y * 128;
    int lane = tid & 31, wid = tid >> 5;
    int g = lane >> 2, tg = lane & 3;
    int m_w = (wid & 3) * 32;
    int n_w = (wid >> 2) * 48;

    float acc[2][6][4] = {};

    for (int k0 = 0; k0 < HH; k0 += 32) {
        {
            int k4 = (tid & 7) * 4;
            #pragma unroll
            for (int i = 0; i < 4; ++i) {
                int ml = (tid >> 3) + i * 32;
                int gm = row0 + ml;
                float4 v = make_float4(0.f, 0.f, 0.f, 0.f);
                if (gm < NN)
                    v = *reinterpret_cast<const float4*>(g_h1 + (size_t)gm * HH + k0 + k4);
                As[ml][k4 + 0] = __float_as_uint(v.x);
                As[ml][k4 + 1] = __float_as_uint(v.y);
                As[ml][k4 + 2] = __float_as_uint(v.z);
                As[ml][k4 + 3] = __float_as_uint(v.w);
            }
        }
        {
            #pragma unroll
            for (int i = 0; i < 12; ++i) {
                int idx = tid + i * 256;
                int kk = idx / 96, n = idx % 96;
                Bs[kk][n] = __float_as_uint(g_w2[(size_t)(k0 + kk) * 96 + n]);
            }
        }
        __syncthreads();

        #pragma unroll
        for (int ks = 0; ks < 4; ++ks) {
            int kk = ks * 8 + tg;
            unsigned af[2][4];
            #pragma unroll
            for (int mt = 0; mt < 2; ++mt) {
                int m = m_w + mt * 16;
                af[mt][0] = As[m + g][kk];
                af[mt][1] = As[m + g + 8][kk];
                af[mt][2] = As[m + g][kk + 4];
                af[mt][3] = As[m + g + 8][kk + 4];
            }
            unsigned bf[6][2];
            #pragma unroll
            for (int nt = 0; nt < 6; ++nt) {
                int n = n_w + nt * 8 + g;
                bf[nt][0] = Bs[kk][n];
                bf[nt][1] = Bs[kk + 4][n];
            }
            #pragma unroll
            for (int mt = 0; mt < 2; ++mt)
                #pragma unroll
                for (int nt = 0; nt < 6; ++nt)
                    mma_tf32(acc[mt][nt], af[mt][0], af[mt][1], af[mt][2], af[mt][3],
                             bf[nt][0], bf[nt][1]);
        }
        __syncthreads();
    }

    #pragma unroll
    for (int mt = 0; mt < 2; ++mt) {
        int mb = row0 + m_w + mt * 16 + g;
        #pragma unroll
        for (int nt = 0; nt < 6; ++nt) {
            int n = n_w + nt * 8 + 2 * tg;
            float* dst = (n < CP) ? (g_z + n) : (g_s + (n - CP));
            if (mb < NN) {
                float2 r = make_float2(acc[mt][nt][0], acc[mt][nt][1]);
                *reinterpret_cast<float2*>(dst + (size_t)mb * CP) = r;
            }
            if (mb + 8 < NN) {
                float2 r = make_float2(acc[mt][nt][2], acc[mt][nt][3]);
                *reinterpret_cast<float2*>(dst + (size_t)(mb + 8) * CP) = r;
            }
        }
    }
}

// ---------------- agg2: aggz = mean of z rows (16 threads per node) ----------
__global__ void k_agg2() {
    int gid = blockIdx.x * blockDim.x + threadIdx.x;
    int node = gid >> 4;
    int t = gid & 15;
    if (node >= NN || t >= 12) return;
    int start = g_rowptr[node], d = g_deg[node];
    float4 acc = make_float4(0.f, 0.f, 0.f, 0.f);
    for (int j = 0; j < d; ++j) {
        int s = g_adj[start + j];
        float4 v = *reinterpret_cast<const float4*>(g_z + (size_t)s * CP + t * 4);
        acc.x += v.x; acc.y += v.y; acc.z += v.z; acc.w += v.w;
    }
    float inv = d > 0 ? 1.0f / (float)d : 0.f;
    float4 r = make_float4(acc.x * inv, acc.y * inv, acc.z * inv, acc.w * inv);
    *reinterpret_cast<float4*>(g_aggz + (size_t)node * CP + t * 4) = r;
}

// ---------------- loss --------------------------------------------------------
__global__ void k_loss(const int* __restrict__ y,
                       const void* __restrict__ maskp,
                       const float* __restrict__ b2n,
                       const float* __restrict__ b2s) {
    int w = (blockIdx.x * blockDim.x + threadIdx.x) >> 5;
    int lane = threadIdx.x & 31;
    if (w >= NN) return;
    const float* az = g_aggz + (size_t)w * CP;
    const float* ss = g_s    + (size_t)w * CP;

    int j2 = lane + 32;
    float l1 = az[lane] + ss[lane] + b2n[lane] + b2s[lane];
    float l2 = -1e30f;
    if (j2 < CC) l2 = az[j2] + ss[j2] + b2n[j2] + b2s[j2];

    float m = fmaxf(l1, l2);
    #pragma unroll
    for (int o = 16; o; o >>= 1) m = fmaxf(m, __shfl_xor_sync(0xffffffffu, m, o));
    float se = expf(l1 - m) + ((j2 < CC) ? expf(l2 - m) : 0.f);
    #pragma unroll
    for (int o = 16; o; o >>= 1) se += __shfl_xor_sync(0xffffffffu, se, o);

    if (lane == 0) {
        bool tm = g_maskwide ? (((const int*)maskp)[w] != 0)
                             : (((const unsigned char*)maskp)[w] != 0);
        if (tm) {
            int yy = y[w];
            float ly = az[yy] + ss[yy] + b2n[yy] + b2s[yy];
            float nll = m + logf(se) - ly;
            atomicAdd(&g_acc[0], nll);
            atomicAdd(&g_acc[1], 1.0f);
        }
    }
}

__global__ void k_fin(float* out) {
    out[0] = g_acc[0] / fmaxf(g_acc[1], 1.0f);
}

// ---------------- host launcher ----------------------------------------------
extern "C" void kernel_launch(void* const* d_in, const int* in_sizes, int n_in,
                              void* d_out, int out_size) {
    const float* x    = (const float*)d_in[0];
    const int*   row  = (const int*)d_in[1];
    const int*   col  = (const int*)d_in[2];
    const int*   y    = (const int*)d_in[3];
    const void*  mask = d_in[4];
    const float* w1n = (const float*)d_in[5];
    const float* b1n = (const float*)d_in[6];
    const float* w1s = (const float*)d_in[7];
    const float* b1s = (const float*)d_in[8];
    const float* w2n = (const float*)d_in[9];
    const float* b2n = (const float*)d_in[10];
    const float* w2s = (const float*)d_in[11];
    const float* b2s = (const float*)d_in[12];
    float* out = (float*)d_out;

    static int smem_set = 0;
    if (!smem_set) {
        cudaFuncSetAttribute(k_gemm1_mma, cudaFuncAttributeMaxDynamicSharedMemorySize,
                             G1_SMEM_FLOATS * 4);
        smem_set = 1;
    }

    void *p_deg, *p_acc;
    cudaGetSymbolAddress(&p_deg, g_deg);
    cudaGetSymbolAddress(&p_acc, g_acc);
    cudaMemsetAsync(p_deg, 0, NN * sizeof(int));
    cudaMemsetAsync(p_acc, 0, 2 * sizeof(float));

    k_initflag<<<1, 1>>>();
    k_maskprobe<<<(NN / 4 + 255) / 256, 256>>>((const unsigned int*)mask);

    // prep (independent of graph build)
    k_prep_x<<<(NN * DIN / 4 + 255) / 256, 256>>>(x);
    k_prep_w1<<<(256 * HH + 255) / 256, 256>>>(w1n, w1s);
    k_prep_w2<<<(HH * 96 + 255) / 256, 256>>>(w2n, w2s);

    // CSR build
    int nb = (NN + 255) / 256;
    k_deg<<<(EE + 255) / 256, 256>>>(row);
    k_scan1<<<nb, 256>>>();
    k_scan2<<<1, 256>>>(nb);
    k_scan3<<<nb, 256>>>();
    k_fill<<<(EE + 255) / 256, 256>>>(row, col);

    // layer 1
    k_agg1<<<(NN * 32 + 255) / 256, 256>>>(x);
    {
        dim3 grid(HH / 128, (NN + 127) / 128);
        k_gemm1_mma<<<grid, 256, G1_SMEM_FLOATS * 4>>>(b1n, b1s);
    }
    // layer 2
    {
        dim3 grid(1, (NN + 127) / 128);
        k_gemm2_mma<<<grid, 256>>>();
    }
    k_agg2<<<(NN * 16 + 255) / 256, 256>>>();

    // loss
    k_loss<<<(NN * 32 + 255) / 256, 256>>>(y, mask, b2n, b2s);
    k_fin<<<1, 1>>>(out);
}

// round 6
// speedup vs baseline: 3.6040x; 1.3064x over previous
#include <cuda_runtime.h>
#include <cuda_bf16.h>
#include <math.h>

#define NN   50000
#define EE   800000
#define DIN  128
#define HH   256
#define CC   47
#define CP   48

// ---------------- scratch (device globals) -----------------------------------
__device__ __nv_bfloat16 g_xh  [(size_t)NN * DIN];   // bf16 copy of x
__device__ __nv_bfloat16 g_aggb[(size_t)NN * DIN];   // bf16 mean of x over in-edges
__device__ __nv_bfloat16 g_h1b [(size_t)NN * HH];    // bf16 layer-1 activations
__device__ __nv_bfloat16 g_w1t [256 * HH];           // [n=256][k=256]  [w1n;w1s]^T
__device__ __nv_bfloat16 g_w2t [96 * HH];            // [n=96][k=256]   [w2n|w2s]^T
__device__ float g_z   [(size_t)NN * CP];            // h1 @ w2n
__device__ float g_s   [(size_t)NN * CP];            // h1 @ w2s
__device__ int   g_deg  [NN];
__device__ int   g_rowptr[NN];
__device__ int   g_cursor[NN];
__device__ int   g_adj  [EE];
__device__ int   g_bsum [256];
__device__ int   g_misc [4];   // [0]=byte-mask flag, [2..3]=loss acc (float bits)

__device__ __forceinline__ void mma_bf16(float c[4],
        unsigned a0, unsigned a1, unsigned a2, unsigned a3,
        unsigned b0, unsigned b1) {
    asm volatile("mma.sync.aligned.m16n8k16.row.col.f32.bf16.bf16.f32 "
                 "{%0,%1,%2,%3},{%4,%5,%6,%7},{%8,%9},{%0,%1,%2,%3};"
                 : "+f"(c[0]), "+f"(c[1]), "+f"(c[2]), "+f"(c[3])
                 : "r"(a0), "r"(a1), "r"(a2), "r"(a3), "r"(b0), "r"(b1));
}
__device__ __forceinline__ void ldsm4(unsigned &r0, unsigned &r1, unsigned &r2, unsigned &r3,
                                      const void* p) {
    unsigned a = (unsigned)__cvta_generic_to_shared(p);
    asm volatile("ldmatrix.sync.aligned.m8n8.x4.shared.b16 {%0,%1,%2,%3}, [%4];"
                 : "=r"(r0), "=r"(r1), "=r"(r2), "=r"(r3) : "r"(a));
}
__device__ __forceinline__ void ldsm2(unsigned &r0, unsigned &r1, const void* p) {
    unsigned a = (unsigned)__cvta_generic_to_shared(p);
    asm volatile("ldmatrix.sync.aligned.m8n8.x2.shared.b16 {%0,%1}, [%2];"
                 : "=r"(r0), "=r"(r1) : "r"(a));
}
__device__ __forceinline__ void cpa16(void* dst, const void* src, bool p) {
    unsigned d = (unsigned)__cvta_generic_to_shared(dst);
    int sz = p ? 16 : 0;
    asm volatile("cp.async.ca.shared.global [%0], [%1], 16, %2;"
                 :: "r"(d), "l"(src), "r"(sz) : "memory");
}

// ---------------- K: mask probe + degree count -------------------------------
__global__ void k_probe_deg(const int* __restrict__ row,
                            const unsigned int* __restrict__ mw) {
    int e = blockIdx.x * blockDim.x + threadIdx.x;
    if (e < NN / 4 && mw[e] > 1u) g_misc[0] = 1;      // byte-packed mask detected
    if (e < EE) atomicAdd(&g_deg[row[e]], 1);
}

// ---------------- scan (3-phase) ---------------------------------------------
__global__ void k_scan1() {
    __shared__ int sh[256];
    int i = blockIdx.x * 256 + threadIdx.x;
    int v = (i < NN) ? g_deg[i] : 0;
    sh[threadIdx.x] = v;
    __syncthreads();
    for (int o = 1; o < 256; o <<= 1) {
        int t = (threadIdx.x >= o) ? sh[threadIdx.x - o] : 0;
        __syncthreads();
        sh[threadIdx.x] += t;
        __syncthreads();
    }
    int incl = sh[threadIdx.x];
    if (i < NN) g_rowptr[i] = incl - v;
    if (threadIdx.x == 255) g_bsum[blockIdx.x] = incl;
}
__global__ void k_scan2(int nb) {
    __shared__ int sh[256];
    int b = threadIdx.x;
    int v = (b < nb) ? g_bsum[b] : 0;
    sh[b] = v;
    __syncthreads();
    for (int o = 1; o < 256; o <<= 1) {
        int t = (b >= o) ? sh[b - o] : 0;
        __syncthreads();
        sh[b] += t;
        __syncthreads();
    }
    g_bsum[b] = sh[b] - v;
}
__global__ void k_scan3() {
    int i = blockIdx.x * 256 + threadIdx.x;
    if (i >= NN) return;
    int rp = g_rowptr[i] + g_bsum[i >> 8];
    g_rowptr[i] = rp;
    g_cursor[i] = rp;
}
__global__ void k_fill(const int* __restrict__ row, const int* __restrict__ col) {
    int e = blockIdx.x * blockDim.x + threadIdx.x;
    if (e >= EE) return;
    int pos = atomicAdd(&g_cursor[row[e]], 1);
    g_adj[pos] = col[e];
}

// ---------------- fused prep: bf16 packs -------------------------------------
// range 0: x -> g_xh (as bf162 pairs, 3.2M items)
// range 1: w1 -> g_w1t [n][k] (65536)
// range 2: w2 -> g_w2t [n][k] (24576)
#define PREP_X  (NN * DIN / 2)
#define PREP_W1 (256 * HH)
#define PREP_W2 (96 * HH)
__global__ void k_prep(const float* __restrict__ x,
                       const float* __restrict__ w1n, const float* __restrict__ w1s,
                       const float* __restrict__ w2n, const float* __restrict__ w2s) {
    int i = blockIdx.x * blockDim.x + threadIdx.x;
    int total = PREP_X + PREP_W1 + PREP_W2;
    for (; i < total; i += gridDim.x * blockDim.x) {
        if (i < PREP_X) {
            float2 v = reinterpret_cast<const float2*>(x)[i];
            reinterpret_cast<__nv_bfloat162*>(g_xh)[i] = __float22bfloat162_rn(v);
        } else if (i < PREP_X + PREP_W1) {
            int j = i - PREP_X;
            int n = j >> 8, k = j & 255;
            float v = (k < DIN) ? w1n[k * HH + n] : w1s[(k - DIN) * HH + n];
            g_w1t[n * 256 + k] = __float2bfloat16(v);
        } else {
            int j = i - PREP_X - PREP_W1;
            int n = j >> 8, k = j & 255;
            float v = 0.f;
            if (n < CP) { if (n < CC) v = w2n[k * CC + n]; }
            else        { int n2 = n - CP; if (n2 < CC) v = w2s[k * CC + n2]; }
            g_w2t[n * 256 + k] = __float2bfloat16(v);
        }
    }
}

// ---------------- agg1: aggb = bf16(mean of bf16 x rows), warp per node ------
__global__ void k_agg1() {
    int w = (blockIdx.x * blockDim.x + threadIdx.x) >> 5;
    int lane = threadIdx.x & 31;
    if (w >= NN) return;
    int start = g_rowptr[w], d = g_deg[w];
    float4 acc = make_float4(0.f, 0.f, 0.f, 0.f);
    for (int j = 0; j < d; ++j) {
        int s = g_adj[start + j];
        uint2 u = reinterpret_cast<const uint2*>(g_xh + (size_t)s * DIN)[lane];
        float2 a = __bfloat1622float2(*reinterpret_cast<__nv_bfloat162*>(&u.x));
        float2 b = __bfloat1622float2(*reinterpret_cast<__nv_bfloat162*>(&u.y));
        acc.x += a.x; acc.y += a.y; acc.z += b.x; acc.w += b.y;
    }
    float inv = d > 0 ? 1.0f / (float)d : 0.f;
    uint2 r;
    *reinterpret_cast<__nv_bfloat162*>(&r.x) =
        __float22bfloat162_rn(make_float2(acc.x * inv, acc.y * inv));
    *reinterpret_cast<__nv_bfloat162*>(&r.y) =
        __float22bfloat162_rn(make_float2(acc.z * inv, acc.w * inv));
    reinterpret_cast<uint2*>(g_aggb + (size_t)w * DIN)[lane] = r;
}

// ---------------- GEMM1 (bf16 mma): h1 = relu([aggb|xh] @ w1t^T + b) ---------
// block 128x128, K=256 in 4 tiles of 64, double-buffered cp.async
// smem: A[2][128][72] bf16, B(nk)[2][128][72] bf16, bias[128] f32
#define G1_SMEM (2*128*72*2 + 2*128*72*2 + 128*4)
__global__ __launch_bounds__(256) void k_gemm1(
        const float* __restrict__ b1n, const float* __restrict__ b1s) {
    extern __shared__ __nv_bfloat16 sm[];
    __nv_bfloat16* As = sm;                       // [2][128][72]
    __nv_bfloat16* Bs = sm + 2 * 128 * 72;        // [2][128][72]  ([n][k])
    float* sbias = reinterpret_cast<float*>(Bs + 2 * 128 * 72);

    int tid  = threadIdx.x;
    int row0 = blockIdx.y * 128;
    int col0 = blockIdx.x * 128;
    if (tid < 128) sbias[tid] = b1n[col0 + tid] + b1s[col0 + tid];

    int lane = tid & 31, wid = tid >> 5;
    int m_w = (wid & 1) * 64;
    int n_w = (wid >> 1) * 32;

#define AS1(s,m,k) (As + ((s)*128 + (m))*72 + (k))
#define BS1(s,n,k) (Bs + ((s)*128 + (n))*72 + (k))

    auto load_tiles = [&](int s, int kt) {
        #pragma unroll
        for (int i = 0; i < 4; ++i) {
            int idx = tid + i * 256;
            int r = idx >> 3, c = (idx & 7) * 8;
            int gm = row0 + r;
            bool p = gm < NN;
            int gmc = p ? gm : 0;
            const __nv_bfloat16* src = (kt < 2)
                ? g_aggb + (size_t)gmc * DIN + kt * 64 + c
                : g_xh   + (size_t)gmc * DIN + (kt - 2) * 64 + c;
            cpa16(AS1(s, r, c), src, p);
        }
        #pragma unroll
        for (int i = 0; i < 4; ++i) {
            int idx = tid + i * 256;
            int r = idx >> 3, c = (idx & 7) * 8;
            cpa16(BS1(s, r, c), g_w1t + (size_t)(col0 + r) * 256 + kt * 64 + c, true);
        }
    };

    float acc[4][4][4] = {};
    load_tiles(0, 0);
    asm volatile("cp.async.commit_group;" ::: "memory");

    for (int kt = 0; kt < 4; ++kt) {
        if (kt + 1 < 4) {
            load_tiles((kt + 1) & 1, kt + 1);
            asm volatile("cp.async.commit_group;" ::: "memory");
            asm volatile("cp.async.wait_group 1;" ::: "memory");
        } else {
            asm volatile("cp.async.wait_group 0;" ::: "memory");
        }
        __syncthreads();
        int buf = kt & 1;
        #pragma unroll
        for (int ks = 0; ks < 4; ++ks) {
            int kk = ks * 16;
            unsigned af[4][4];
            #pragma unroll
            for (int mt = 0; mt < 4; ++mt) {
                int m = m_w + mt * 16 + (lane & 15);
                int c = kk + (lane >> 4) * 8;
                ldsm4(af[mt][0], af[mt][1], af[mt][2], af[mt][3], AS1(buf, m, c));
            }
            unsigned bf[4][2];
            #pragma unroll
            for (int nt = 0; nt < 4; ++nt) {
                int n = n_w + nt * 8 + (lane & 7);
                int c = kk + ((lane >> 3) & 1) * 8;
                ldsm2(bf[nt][0], bf[nt][1], BS1(buf, n, c));
            }
            #pragma unroll
            for (int mt = 0; mt < 4; ++mt)
                #pragma unroll
                for (int nt = 0; nt < 4; ++nt)
                    mma_bf16(acc[mt][nt], af[mt][0], af[mt][1], af[mt][2], af[mt][3],
                             bf[nt][0], bf[nt][1]);
        }
        __syncthreads();
    }

    int g = lane >> 2, tg = lane & 3;
    #pragma unroll
    for (int mt = 0; mt < 4; ++mt) {
        int mb = row0 + m_w + mt * 16 + g;
        #pragma unroll
        for (int nt = 0; nt < 4; ++nt) {
            int nl = n_w + nt * 8 + 2 * tg;
            int gn = col0 + nl;
            float b0 = sbias[nl], b1 = sbias[nl + 1];
            if (mb < NN) {
                __nv_bfloat162 r = __float22bfloat162_rn(
                    make_float2(fmaxf(acc[mt][nt][0] + b0, 0.f),
                                fmaxf(acc[mt][nt][1] + b1, 0.f)));
                *reinterpret_cast<__nv_bfloat162*>(g_h1b + (size_t)mb * HH + gn) = r;
            }
            if (mb + 8 < NN) {
                __nv_bfloat162 r = __float22bfloat162_rn(
                    make_float2(fmaxf(acc[mt][nt][2] + b0, 0.f),
                                fmaxf(acc[mt][nt][3] + b1, 0.f)));
                *reinterpret_cast<__nv_bfloat162*>(g_h1b + (size_t)(mb + 8) * HH + gn) = r;
            }
        }
    }
}

// ---------------- GEMM2 (bf16 mma): [z|s] = h1b @ w2t^T ----------------------
// block 128x96, K=256 in 4 tiles of 64; 8 warps 4m x 2n (warp 32x48)
#define G2_SMEM (2*128*72*2 + 2*96*72*2)
__global__ __launch_bounds__(256) void k_gemm2() {
    extern __shared__ __nv_bfloat16 sm[];
    __nv_bfloat16* As = sm;                  // [2][128][72]
    __nv_bfloat16* Bs = sm + 2 * 128 * 72;   // [2][96][72]

    int tid  = threadIdx.x;
    int row0 = blockIdx.y * 128;
    int lane = tid & 31, wid = tid >> 5;
    int m_w = (wid & 3) * 32;
    int n_w = (wid >> 2) * 48;

#define AS2(s,m,k) (As + ((s)*128 + (m))*72 + (k))
#define BS2(s,n,k) (Bs + ((s)*96 + (n))*72 + (k))

    auto load_tiles = [&](int s, int kt) {
        #pragma unroll
        for (int i = 0; i < 4; ++i) {
            int idx = tid + i * 256;
            int r = idx >> 3, c = (idx & 7) * 8;
            int gm = row0 + r;
            bool p = gm < NN;
            int gmc = p ? gm : 0;
            cpa16(AS2(s, r, c), g_h1b + (size_t)gmc * HH + kt * 64 + c, p);
        }
        #pragma unroll
        for (int i = 0; i < 3; ++i) {
            int idx = tid + i * 256;
            int r = idx >> 3, c = (idx & 7) * 8;
            cpa16(BS2(s, r, c), g_w2t + (size_t)r * 256 + kt * 64 + c, true);
        }
    };

    float acc[2][6][4] = {};
    load_tiles(0, 0);
    asm volatile("cp.async.commit_group;" ::: "memory");

    for (int kt = 0; kt < 4; ++kt) {
        if (kt + 1 < 4) {
            load_tiles((kt + 1) & 1, kt + 1);
            asm volatile("cp.async.commit_group;" ::: "memory");
            asm volatile("cp.async.wait_group 1;" ::: "memory");
        } else {
            asm volatile("cp.async.wait_group 0;" ::: "memory");
        }
        __syncthreads();
        int buf = kt & 1;
        #pragma unroll
        for (int ks = 0; ks < 4; ++ks) {
            int kk = ks * 16;
            unsigned af[2][4];
            #pragma unroll
            for (int mt = 0; mt < 2; ++mt) {
                int m = m_w + mt * 16 + (lane & 15);
                int c = kk + (lane >> 4) * 8;
                ldsm4(af[mt][0], af[mt][1], af[mt][2], af[mt][3], AS2(buf, m, c));
            }
            unsigned bf[6][2];
            #pragma unroll
            for (int nt = 0; nt < 6; ++nt) {
                int n = n_w + nt * 8 + (lane & 7);
                int c = kk + ((lane >> 3) & 1) * 8;
                ldsm2(bf[nt][0], bf[nt][1], BS2(buf, n, c));
            }
            #pragma unroll
            for (int mt = 0; mt < 2; ++mt)
                #pragma unroll
                for (int nt = 0; nt < 6; ++nt)
                    mma_bf16(acc[mt][nt], af[mt][0], af[mt][1], af[mt][2], af[mt][3],
                             bf[nt][0], bf[nt][1]);
        }
        __syncthreads();
    }

    int g = lane >> 2, tg = lane & 3;
    #pragma unroll
    for (int mt = 0; mt < 2; ++mt) {
        int mb = row0 + m_w + mt * 16 + g;
        #pragma unroll
        for (int nt = 0; nt < 6; ++nt) {
            int n = n_w + nt * 8 + 2 * tg;
            float* dst = (n < CP) ? (g_z + n) : (g_s + (n - CP));
            if (mb < NN)
                *reinterpret_cast<float2*>(dst + (size_t)mb * CP) =
                    make_float2(acc[mt][nt][0], acc[mt][nt][1]);
            if (mb + 8 < NN)
                *reinterpret_cast<float2*>(dst + (size_t)(mb + 8) * CP) =
                    make_float2(acc[mt][nt][2], acc[mt][nt][3]);
        }
    }
}

// ---------------- fused agg2 + loss: warp per node ---------------------------
__global__ void k_loss(const int* __restrict__ y,
                       const void* __restrict__ maskp,
                       const float* __restrict__ b2n,
                       const float* __restrict__ b2s) {
    __shared__ float sz[8][52];
    int w = (blockIdx.x * blockDim.x + threadIdx.x) >> 5;
    int lane = threadIdx.x & 31;
    int wl = (threadIdx.x >> 5) & 7;
    if (w >= NN) return;

    int start = g_rowptr[w], d = g_deg[w];
    float4 acc = make_float4(0.f, 0.f, 0.f, 0.f);
    if (lane < 12) {
        for (int j = 0; j < d; ++j) {
            int s = g_adj[start + j];
            float4 v = reinterpret_cast<const float4*>(g_z + (size_t)s * CP)[lane];
            acc.x += v.x; acc.y += v.y; acc.z += v.z; acc.w += v.w;
        }
        float inv = d > 0 ? 1.0f / (float)d : 0.f;
        sz[wl][lane * 4 + 0] = acc.x * inv;
        sz[wl][lane * 4 + 1] = acc.y * inv;
        sz[wl][lane * 4 + 2] = acc.z * inv;
        sz[wl][lane * 4 + 3] = acc.w * inv;
    }
    __syncwarp();

    const float* ss = g_s + (size_t)w * CP;
    int j2 = lane + 32;
    float l1 = sz[wl][lane] + ss[lane] + b2n[lane] + b2s[lane];
    float l2 = -1e30f;
    if (j2 < CC) l2 = sz[wl][j2] + ss[j2] + b2n[j2] + b2s[j2];

    float m = fmaxf(l1, l2);
    #pragma unroll
    for (int o = 16; o; o >>= 1) m = fmaxf(m, __shfl_xor_sync(0xffffffffu, m, o));
    float se = expf(l1 - m) + ((j2 < CC) ? expf(l2 - m) : 0.f);
    #pragma unroll
    for (int o = 16; o; o >>= 1) se += __shfl_xor_sync(0xffffffffu, se, o);

    // locate ly: class y[w]
    if (lane == 0) {
        bool bytemode = (g_misc[0] != 0);
        bool tm = bytemode ? (((const unsigned char*)maskp)[w] != 0)
                           : (((const int*)maskp)[w] != 0);
        if (tm) {
            int yy = y[w];
            float ly = sz[wl][yy] + ss[yy] + b2n[yy] + b2s[yy];
            float nll = m + logf(se) - ly;
            atomicAdd(reinterpret_cast<float*>(&g_misc[2]), nll);
            atomicAdd(reinterpret_cast<float*>(&g_misc[3]), 1.0f);
        }
    }
}

__global__ void k_fin(float* out) {
    float a = __int_as_float(g_misc[2]);
    float c = __int_as_float(g_misc[3]);
    out[0] = a / fmaxf(c, 1.0f);
}

// ---------------- host launcher ----------------------------------------------
extern "C" void kernel_launch(void* const* d_in, const int* in_sizes, int n_in,
                              void* d_out, int out_size) {
    const float* x    = (const float*)d_in[0];
    const int*   row  = (const int*)d_in[1];
    const int*   col  = (const int*)d_in[2];
    const int*   y    = (const int*)d_in[3];
    const void*  mask = d_in[4];
    const float* w1n = (const float*)d_in[5];
    const float* b1n = (const float*)d_in[6];
    const float* w1s = (const float*)d_in[7];
    const float* b1s = (const float*)d_in[8];
    const float* w2n = (const float*)d_in[9];
    const float* b2n = (const float*)d_in[10];
    const float* w2s = (const float*)d_in[11];
    const float* b2s = (const float*)d_in[12];
    float* out = (float*)d_out;

    static int cfg = 0;
    if (!cfg) {
        cudaFuncSetAttribute(k_gemm1, cudaFuncAttributeMaxDynamicSharedMemorySize, G1_SMEM);
        cudaFuncSetAttribute(k_gemm2, cudaFuncAttributeMaxDynamicSharedMemorySize, G2_SMEM);
        cfg = 1;
    }

    void *p_deg, *p_misc;
    cudaGetSymbolAddress(&p_deg,  g_deg);
    cudaGetSymbolAddress(&p_misc, g_misc);
    cudaMemsetAsync(p_deg,  0, NN * sizeof(int));
    cudaMemsetAsync(p_misc, 0, 4 * sizeof(int));

    k_probe_deg<<<(EE + 255) / 256, 256>>>(row, (const unsigned int*)mask);
    k_prep<<<2048, 256>>>(x, w1n, w1s, w2n, w2s);

    int nb = (NN + 255) / 256;
    k_scan1<<<nb, 256>>>();
    k_scan2<<<1, 256>>>(nb);
    k_scan3<<<nb, 256>>>();
    k_fill<<<(EE + 255) / 256, 256>>>(row, col);

    k_agg1<<<(NN * 32 + 255) / 256, 256>>>();
    {
        dim3 grid(HH / 128, (NN + 127) / 128);
        k_gemm1<<<grid, 256, G1_SMEM>>>(b1n, b1s);
    }
    {
        dim3 grid(1, (NN + 127) / 128);
        k_gemm2<<<grid, 256, G2_SMEM>>>();
    }
    k_loss<<<(NN * 32 + 255) / 256, 256>>>(y, mask, b2n, b2s);
    k_fin<<<1, 1>>>(out);
}